// round 14
// baseline (speedup 1.0000x reference)
#include <cuda_runtime.h>
#include <math.h>

#define B_   32
#define T_   64
#define V_   32000
#define E_   512
#define H_   1024
#define BOS_ 1
#define EOS_ 3

#define TILE_V  128
#define NBLK_V  250   // 250 * 128 = 32000 exactly

// ---------------- device scratch (no cudaMalloc allowed) ----------------
__device__ float g_h[2][B_ * H_];      // ping-pong hidden state
__device__ float g_c[B_ * H_];         // cell state (in-place safe: 1 owner per elem)
__device__ float g_pScore[NBLK_V * B_];
__device__ int   g_pIdx[NBLK_V * B_];
__device__ int   g_labels[T_ * B_];

// ---------------- helpers ----------------
__device__ __forceinline__ float sigm_(float x) {
    if (x >= 0.f) return 1.f / (1.f + expf(-x));
    float e = expf(x);
    return e / (1.f + e);
}

// ---------------- score + per-block argmax ----------------
// scores[b][v] = dot(h[b,:], W_hv[v,:]) + b_hv[v] + gumbel(u[t,b,v])
// lane == b; each warp owns 16 consecutive v's; block covers 128 v's, all 32 b.
__global__ __launch_bounds__(256) void score_kernel(
        int cur,
        const float* __restrict__ Whv,
        const float* __restrict__ bhv,
        const float* __restrict__ u_t) {
    __shared__ float hT[128 * 33];      // h chunk transposed, pad 33 (conflict-free)
    __shared__ float sBest[8 * 32];
    __shared__ int   sIdx[8 * 32];

    const int tid  = threadIdx.x;
    const int lane = tid & 31;          // = batch index b
    const int w    = tid >> 5;          // warp id 0..7
    const int vBase = blockIdx.x * TILE_V + w * 16;
    const float* __restrict__ h = g_h[cur];

    float acc[16];
#pragma unroll
    for (int i = 0; i < 16; i++) acc[i] = 0.f;

    const float* WB = Whv + (size_t)vBase * H_;

    for (int kc = 0; kc < H_; kc += 128) {
        // stage h[:, kc:kc+128] transposed into smem (coalesced read, conflict-free write)
        for (int idx = tid; idx < B_ * 128; idx += 256) {
            int b = idx >> 7, k = idx & 127;
            hT[k * 33 + b] = h[b * H_ + kc + k];
        }
        __syncthreads();
#pragma unroll 2
        for (int k4 = 0; k4 < 32; k4++) {
            float h0 = hT[(k4 * 4 + 0) * 33 + lane];
            float h1 = hT[(k4 * 4 + 1) * 33 + lane];
            float h2 = hT[(k4 * 4 + 2) * 33 + lane];
            float h3 = hT[(k4 * 4 + 3) * 33 + lane];
            const float* Wk = WB + kc + k4 * 4;
#pragma unroll
            for (int i = 0; i < 16; i++) {
                float4 wv = *reinterpret_cast<const float4*>(Wk + (size_t)i * H_);
                float a = acc[i];
                a = fmaf(wv.x, h0, a);
                a = fmaf(wv.y, h1, a);
                a = fmaf(wv.z, h2, a);
                a = fmaf(wv.w, h3, a);
                acc[i] = a;
            }
        }
        __syncthreads();
    }

    // bias + gumbel noise + per-thread argmax (ascending v => strict '>' = first-max)
    float best = -3.402823466e38f;
    int bestV = 0;
    const float* urow = u_t + (size_t)lane * V_;
#pragma unroll
    for (int i = 0; i < 16; i++) {
        int v = vBase + i;
        float uu = urow[v];
        float gn = -logf(-logf(uu + 1e-10f) + 1e-10f);
        float s = acc[i] + bhv[v] + gn;
        if (s > best) { best = s; bestV = v; }
    }
    sBest[w * 32 + lane] = best;
    sIdx[w * 32 + lane]  = bestV;
    __syncthreads();

    if (tid < 32) {   // combine 8 warps for batch b = tid
        float bb = sBest[tid];
        int   bi = sIdx[tid];
        for (int ww = 1; ww < 8; ww++) {
            float s = sBest[ww * 32 + tid];
            int   v = sIdx[ww * 32 + tid];
            if (s > bb || (s == bb && v < bi)) { bb = s; bi = v; }
        }
        g_pScore[blockIdx.x * B_ + tid] = bb;
        g_pIdx[blockIdx.x * B_ + tid]   = bi;
    }
}

// ---------------- LSTM step (fused: final argmax reduce -> x=emb[label] -> gates -> h,c) ----------------
// grid 128 blocks, 128 threads. lane == b; each warp owns 2 m-values (all 4 gates) => block owns 8 m.
__global__ __launch_bounds__(128) void lstm_kernel(
        int cur,
        const float* __restrict__ emb,
        const float* __restrict__ Wih,
        const float* __restrict__ Whh,
        const float* __restrict__ bih,
        const float* __restrict__ bhh,
        int useArgmax, int tstep) {
    __shared__ float sT[128 * 33];
    __shared__ int   labelS[B_];
    __shared__ float rs[4 * 32];
    __shared__ int   ri[4 * 32];

    const int tid  = threadIdx.x;
    const int lane = tid & 31;
    const int w    = tid >> 5;

    if (useArgmax) {
        // redundant (per-block) deterministic reduction of 250 partials per batch
        int r = tid & 3, b = tid >> 2;
        float bb = -3.402823466e38f;
        int   bi = 0x7fffffff;
        for (int j = r; j < NBLK_V; j += 4) {
            float s = g_pScore[j * B_ + b];
            int   v = g_pIdx[j * B_ + b];
            if (s > bb || (s == bb && v < bi)) { bb = s; bi = v; }
        }
        rs[r * 32 + b] = bb;
        ri[r * 32 + b] = bi;
        __syncthreads();
        if (tid < 32) {
            float m = rs[tid];
            int  mi = ri[tid];
            for (int r2 = 1; r2 < 4; r2++) {
                float s = rs[r2 * 32 + tid];
                int   v = ri[r2 * 32 + tid];
                if (s > m || (s == m && v < mi)) { m = s; mi = v; }
            }
            labelS[tid] = mi;
            if (blockIdx.x == 0) g_labels[tstep * B_ + tid] = mi;
        }
    } else {
        if (tid < 32) labelS[tid] = BOS_;   // initial step: x0 = emb[BOS]
    }
    __syncthreads();

    const float* __restrict__ hin = g_h[cur];
    float* __restrict__ hout = g_h[cur ^ 1];
    const int m0 = blockIdx.x * 8 + w * 2;

    float a[8];   // [mm(2)][gate(4)] : i,f,g,o
#pragma unroll
    for (int i = 0; i < 8; i++) a[i] = 0.f;

    // ---- x @ W_ih^T  (x[b] = emb[label_b], E = 512) ----
    for (int ec = 0; ec < E_; ec += 128) {
        for (int idx = tid; idx < B_ * 128; idx += 128) {
            int b = idx >> 7, k = idx & 127;
            sT[k * 33 + b] = emb[(size_t)labelS[b] * E_ + ec + k];
        }
        __syncthreads();
#pragma unroll 2
        for (int k4 = 0; k4 < 32; k4++) {
            float x0 = sT[(k4 * 4 + 0) * 33 + lane];
            float x1 = sT[(k4 * 4 + 1) * 33 + lane];
            float x2 = sT[(k4 * 4 + 2) * 33 + lane];
            float x3 = sT[(k4 * 4 + 3) * 33 + lane];
#pragma unroll
            for (int mm = 0; mm < 2; mm++)
#pragma unroll
                for (int gg = 0; gg < 4; gg++) {
                    int j = m0 + mm + gg * H_;
                    float4 wv = *reinterpret_cast<const float4*>(
                        Wih + (size_t)j * E_ + ec + k4 * 4);
                    float v = a[mm * 4 + gg];
                    v = fmaf(wv.x, x0, v); v = fmaf(wv.y, x1, v);
                    v = fmaf(wv.z, x2, v); v = fmaf(wv.w, x3, v);
                    a[mm * 4 + gg] = v;
                }
        }
        __syncthreads();
    }
    // ---- h @ W_hh^T  (H = 1024) ----
    for (int hc = 0; hc < H_; hc += 128) {
        for (int idx = tid; idx < B_ * 128; idx += 128) {
            int b = idx >> 7, k = idx & 127;
            sT[k * 33 + b] = hin[b * H_ + hc + k];
        }
        __syncthreads();
#pragma unroll 2
        for (int k4 = 0; k4 < 32; k4++) {
            float x0 = sT[(k4 * 4 + 0) * 33 + lane];
            float x1 = sT[(k4 * 4 + 1) * 33 + lane];
            float x2 = sT[(k4 * 4 + 2) * 33 + lane];
            float x3 = sT[(k4 * 4 + 3) * 33 + lane];
#pragma unroll
            for (int mm = 0; mm < 2; mm++)
#pragma unroll
                for (int gg = 0; gg < 4; gg++) {
                    int j = m0 + mm + gg * H_;
                    float4 wv = *reinterpret_cast<const float4*>(
                        Whh + (size_t)j * H_ + hc + k4 * 4);
                    float v = a[mm * 4 + gg];
                    v = fmaf(wv.x, x0, v); v = fmaf(wv.y, x1, v);
                    v = fmaf(wv.z, x2, v); v = fmaf(wv.w, x3, v);
                    a[mm * 4 + gg] = v;
                }
        }
        __syncthreads();
    }

#pragma unroll
    for (int mm = 0; mm < 2; mm++) {
        int m = m0 + mm;
        float gi = a[mm * 4 + 0] + bih[m]          + bhh[m];
        float gf = a[mm * 4 + 1] + bih[m + H_]     + bhh[m + H_];
        float gc = a[mm * 4 + 2] + bih[m + 2 * H_] + bhh[m + 2 * H_];
        float go = a[mm * 4 + 3] + bih[m + 3 * H_] + bhh[m + 3 * H_];
        float co = g_c[lane * H_ + m];
        float cn = sigm_(gf) * co + sigm_(gi) * tanhf(gc);
        float hn = sigm_(go) * tanhf(cn);
        g_c[lane * H_ + m] = cn;
        hout[lane * H_ + m] = hn;
    }
}

// ---------------- h0 = image_hidden @ W_proj^T + b_proj ; c = 0 ----------------
__global__ __launch_bounds__(128) void inith_kernel(
        const float* __restrict__ img,
        const float* __restrict__ Wproj,
        const float* __restrict__ bproj) {
    __shared__ float sT[128 * 33];
    const int tid = threadIdx.x, lane = tid & 31, w = tid >> 5;
    const int m0 = blockIdx.x * 8 + w * 2;
    float a0 = 0.f, a1 = 0.f;
    for (int dc = 0; dc < 1024; dc += 128) {
        for (int idx = tid; idx < B_ * 128; idx += 128) {
            int b = idx >> 7, k = idx & 127;
            sT[k * 33 + b] = img[b * 1024 + dc + k];
        }
        __syncthreads();
#pragma unroll 2
        for (int k4 = 0; k4 < 32; k4++) {
            float x0 = sT[(k4 * 4 + 0) * 33 + lane];
            float x1 = sT[(k4 * 4 + 1) * 33 + lane];
            float x2 = sT[(k4 * 4 + 2) * 33 + lane];
            float x3 = sT[(k4 * 4 + 3) * 33 + lane];
            float4 w0 = *reinterpret_cast<const float4*>(
                Wproj + (size_t)m0 * 1024 + dc + k4 * 4);
            float4 w1 = *reinterpret_cast<const float4*>(
                Wproj + (size_t)(m0 + 1) * 1024 + dc + k4 * 4);
            a0 = fmaf(w0.x, x0, fmaf(w0.y, x1, fmaf(w0.z, x2, fmaf(w0.w, x3, a0))));
            a1 = fmaf(w1.x, x0, fmaf(w1.y, x1, fmaf(w1.z, x2, fmaf(w1.w, x3, a1))));
        }
        __syncthreads();
    }
    g_h[0][lane * H_ + m0]     = a0 + bproj[m0];
    g_h[0][lane * H_ + m0 + 1] = a1 + bproj[m0 + 1];
    g_c[lane * H_ + m0]     = 0.f;
    g_c[lane * H_ + m0 + 1] = 0.f;
}

// ---------------- zero-fill the logits region ----------------
__global__ void zero_kernel(float4* __restrict__ p, long long n4) {
    long long i = (long long)blockIdx.x * blockDim.x + threadIdx.x;
    long long stride = (long long)gridDim.x * blockDim.x;
    float4 z = make_float4(0.f, 0.f, 0.f, 0.f);
    for (; i < n4; i += stride) p[i] = z;
}

// ---------------- assemble outputs: ids, one-hot scatter, lengths ----------------
__global__ __launch_bounds__(256) void final_kernel(float* __restrict__ out) {
    __shared__ int fe[B_];
    const int tid = threadIdx.x;
    if (tid < B_) {
        int f = T_ - 1;                 // labels[T-1] forced to EOS by reference
        for (int t = 0; t < T_ - 1; t++) {
            if (g_labels[t * B_ + tid] == EOS_) { f = t; break; }
        }
        fe[tid] = f;
        out[(long long)B_ * T_ + (long long)B_ * T_ * V_ + tid] = (float)(f + 1);
    }
    __syncthreads();
    for (int idx = tid; idx < B_ * T_; idx += 256) {
        int b = idx >> 6, t = idx & 63;
        int lab = (t == T_ - 1) ? EOS_ : g_labels[t * B_ + b];
        int f = fe[b];
        out[b * T_ + t] = (t < f) ? (float)lab : 0.f;             // message_ids
        int col = (t < f) ? lab : 0;                              // PAD one-hot after EOS
        out[(long long)B_ * T_ + (long long)(b * T_ + t) * V_ + col] = 1.0f;
    }
}

// ---------------- host launcher (graph-capturable: kernels only) ----------------
extern "C" void kernel_launch(void* const* d_in, const int* in_sizes, int n_in,
                              void* d_out, int out_size) {
    const float* img   = (const float*)d_in[0];   // image_hidden [B,D]
    const float* gum   = (const float*)d_in[1];   // gumbel_u [T,B,V]
    const float* Wproj = (const float*)d_in[2];   // [H,D]
    const float* bproj = (const float*)d_in[3];   // [H]
    const float* emb   = (const float*)d_in[4];   // [V,E]
    const float* Wih   = (const float*)d_in[5];   // [4H,E]
    const float* Whh   = (const float*)d_in[6];   // [4H,H]
    const float* bih   = (const float*)d_in[7];   // [4H]
    const float* bhh   = (const float*)d_in[8];   // [4H]
    const float* Whv   = (const float*)d_in[9];   // [V,H]
    const float* bhv   = (const float*)d_in[10];  // [V]
    float* out = (float*)d_out;

    // zero the message_logits region (independent; overlaps nothing it shouldn't)
    zero_kernel<<<4096, 256>>>(reinterpret_cast<float4*>(out + B_ * T_),
                               (long long)B_ * T_ * V_ / 4);

    // init: h0 = proj(image), c = 0; then LSTM with x0 = emb[BOS]
    inith_kernel<<<128, 128>>>(img, Wproj, bproj);
    lstm_kernel<<<128, 128>>>(0, emb, Wih, Whh, bih, bhh, /*useArgmax=*/0, 0);

    int cur = 1;
    // only t = 0..62 matter: reference overwrites step 63's label/logits
    for (int t = 0; t < T_ - 1; t++) {
        score_kernel<<<NBLK_V, 256>>>(cur, Whv, bhv, gum + (size_t)t * B_ * V_);
        lstm_kernel<<<128, 128>>>(cur, emb, Wih, Whh, bih, bhh, /*useArgmax=*/1, t);
        cur ^= 1;
    }

    final_kernel<<<1, 256>>>(out);
}

// round 16
// speedup vs baseline: 2.7360x; 2.7360x over previous
#include <cuda_runtime.h>
#include <math.h>

#define B_   32
#define T_   64
#define V_   32000
#define E_   512
#define H_   1024
#define BOS_ 1
#define EOS_ 3

#define TILE_V 128
#define NBLK_V 250   // 250*128 = 32000
#define KC     16

// ---------------- device scratch ----------------
__device__ float g_h[2][B_ * H_];
__device__ float g_c[B_ * H_];
__device__ float g_pScore[NBLK_V * B_];
__device__ int   g_pIdx[NBLK_V * B_];
__device__ int   g_labels[T_ * B_];

__device__ __forceinline__ float sigm_(float x) {
    if (x >= 0.f) return 1.f / (1.f + expf(-x));
    float e = expf(x);
    return e / (1.f + e);
}

// ================= score kernel v2 =================
// C[v][b] = dot(W_hv[v,:], h[b,:]) ; block tile 128v x 32b, thread tile 8v x 4b.
// Double-buffered smem staging, coalesced global loads.
__global__ __launch_bounds__(128) void score_kernel(
        int cur,
        const float* __restrict__ Whv,
        const float* __restrict__ bhv,
        const float* __restrict__ u_t) {
    __shared__ float sW[2][KC * 128];   // [k][v] transposed tile
    __shared__ float sH[2][KC * 32];    // [k][b]
    __shared__ float redS[32 * 16];
    __shared__ int   redI[32 * 16];

    const int tid = threadIdx.x;
    const int vg = tid & 15;            // 16 v-groups
    const int bg = tid >> 4;            // 8 b-groups
    const int vBase = blockIdx.x * TILE_V;
    const float* __restrict__ h = g_h[cur];

    float acc[8][4];
#pragma unroll
    for (int i = 0; i < 8; i++)
#pragma unroll
        for (int j = 0; j < 4; j++) acc[i][j] = 0.f;

    // staging roles: W -> thread owns tile row r=tid (16 floats / chunk)
    //                h -> thread owns (b = tid>>2, quarter q = tid&3)
    const float* __restrict__ Wrow = Whv + (size_t)(vBase + tid) * H_;
    const int hb = tid >> 2, hq = tid & 3;

    float4 wr0, wr1, wr2, wr3, hr;

    // ---- preload chunk 0 ----
    {
        const float* p = Wrow;
        wr0 = *reinterpret_cast<const float4*>(p + 0);
        wr1 = *reinterpret_cast<const float4*>(p + 4);
        wr2 = *reinterpret_cast<const float4*>(p + 8);
        wr3 = *reinterpret_cast<const float4*>(p + 12);
        hr  = *reinterpret_cast<const float4*>(h + (size_t)hb * H_ + hq * 4);
        float* dW = &sW[0][0];
        dW[(0) * 128 + tid] = wr0.x; dW[(1) * 128 + tid] = wr0.y;
        dW[(2) * 128 + tid] = wr0.z; dW[(3) * 128 + tid] = wr0.w;
        dW[(4) * 128 + tid] = wr1.x; dW[(5) * 128 + tid] = wr1.y;
        dW[(6) * 128 + tid] = wr1.z; dW[(7) * 128 + tid] = wr1.w;
        dW[(8) * 128 + tid] = wr2.x; dW[(9) * 128 + tid] = wr2.y;
        dW[(10) * 128 + tid] = wr2.z; dW[(11) * 128 + tid] = wr2.w;
        dW[(12) * 128 + tid] = wr3.x; dW[(13) * 128 + tid] = wr3.y;
        dW[(14) * 128 + tid] = wr3.z; dW[(15) * 128 + tid] = wr3.w;
        float* dH = &sH[0][0];
        dH[(hq * 4 + 0) * 32 + hb] = hr.x;
        dH[(hq * 4 + 1) * 32 + hb] = hr.y;
        dH[(hq * 4 + 2) * 32 + hb] = hr.z;
        dH[(hq * 4 + 3) * 32 + hb] = hr.w;
    }
    __syncthreads();

    const int NT = H_ / KC;   // 64
    for (int c = 0; c < NT; c++) {
        const int cb = c & 1, nb = (c + 1) & 1;
        if (c + 1 < NT) {
            const float* p = Wrow + (c + 1) * KC;
            wr0 = *reinterpret_cast<const float4*>(p + 0);
            wr1 = *reinterpret_cast<const float4*>(p + 4);
            wr2 = *reinterpret_cast<const float4*>(p + 8);
            wr3 = *reinterpret_cast<const float4*>(p + 12);
            hr  = *reinterpret_cast<const float4*>(h + (size_t)hb * H_ + (c + 1) * KC + hq * 4);
        }
        // ---- compute on buffer cb ----
        const float* cW = &sW[cb][0];
        const float* cH = &sH[cb][0];
#pragma unroll
        for (int k = 0; k < KC; k++) {
            float4 wa = *reinterpret_cast<const float4*>(cW + k * 128 + vg * 4);
            float4 wb = *reinterpret_cast<const float4*>(cW + k * 128 + 64 + vg * 4);
            float4 hv = *reinterpret_cast<const float4*>(cH + k * 32 + bg * 4);
            acc[0][0] = fmaf(wa.x, hv.x, acc[0][0]); acc[0][1] = fmaf(wa.x, hv.y, acc[0][1]);
            acc[0][2] = fmaf(wa.x, hv.z, acc[0][2]); acc[0][3] = fmaf(wa.x, hv.w, acc[0][3]);
            acc[1][0] = fmaf(wa.y, hv.x, acc[1][0]); acc[1][1] = fmaf(wa.y, hv.y, acc[1][1]);
            acc[1][2] = fmaf(wa.y, hv.z, acc[1][2]); acc[1][3] = fmaf(wa.y, hv.w, acc[1][3]);
            acc[2][0] = fmaf(wa.z, hv.x, acc[2][0]); acc[2][1] = fmaf(wa.z, hv.y, acc[2][1]);
            acc[2][2] = fmaf(wa.z, hv.z, acc[2][2]); acc[2][3] = fmaf(wa.z, hv.w, acc[2][3]);
            acc[3][0] = fmaf(wa.w, hv.x, acc[3][0]); acc[3][1] = fmaf(wa.w, hv.y, acc[3][1]);
            acc[3][2] = fmaf(wa.w, hv.z, acc[3][2]); acc[3][3] = fmaf(wa.w, hv.w, acc[3][3]);
            acc[4][0] = fmaf(wb.x, hv.x, acc[4][0]); acc[4][1] = fmaf(wb.x, hv.y, acc[4][1]);
            acc[4][2] = fmaf(wb.x, hv.z, acc[4][2]); acc[4][3] = fmaf(wb.x, hv.w, acc[4][3]);
            acc[5][0] = fmaf(wb.y, hv.x, acc[5][0]); acc[5][1] = fmaf(wb.y, hv.y, acc[5][1]);
            acc[5][2] = fmaf(wb.y, hv.z, acc[5][2]); acc[5][3] = fmaf(wb.y, hv.w, acc[5][3]);
            acc[6][0] = fmaf(wb.z, hv.x, acc[6][0]); acc[6][1] = fmaf(wb.z, hv.y, acc[6][1]);
            acc[6][2] = fmaf(wb.z, hv.z, acc[6][2]); acc[6][3] = fmaf(wb.z, hv.w, acc[6][3]);
            acc[7][0] = fmaf(wb.w, hv.x, acc[7][0]); acc[7][1] = fmaf(wb.w, hv.y, acc[7][1]);
            acc[7][2] = fmaf(wb.w, hv.z, acc[7][2]); acc[7][3] = fmaf(wb.w, hv.w, acc[7][3]);
        }
        if (c + 1 < NT) {
            float* dW = &sW[nb][0];
            dW[(0) * 128 + tid] = wr0.x; dW[(1) * 128 + tid] = wr0.y;
            dW[(2) * 128 + tid] = wr0.z; dW[(3) * 128 + tid] = wr0.w;
            dW[(4) * 128 + tid] = wr1.x; dW[(5) * 128 + tid] = wr1.y;
            dW[(6) * 128 + tid] = wr1.z; dW[(7) * 128 + tid] = wr1.w;
            dW[(8) * 128 + tid] = wr2.x; dW[(9) * 128 + tid] = wr2.y;
            dW[(10) * 128 + tid] = wr2.z; dW[(11) * 128 + tid] = wr2.w;
            dW[(12) * 128 + tid] = wr3.x; dW[(13) * 128 + tid] = wr3.y;
            dW[(14) * 128 + tid] = wr3.z; dW[(15) * 128 + tid] = wr3.w;
            float* dH = &sH[nb][0];
            dH[(hq * 4 + 0) * 32 + hb] = hr.x;
            dH[(hq * 4 + 1) * 32 + hb] = hr.y;
            dH[(hq * 4 + 2) * 32 + hb] = hr.z;
            dH[(hq * 4 + 3) * 32 + hb] = hr.w;
        }
        __syncthreads();
    }

    // ---- bias + gumbel + per-thread argmax (v sets: vg*4+e and 64+vg*4+e) ----
    float4 bv0 = *reinterpret_cast<const float4*>(bhv + vBase + vg * 4);
    float4 bv1 = *reinterpret_cast<const float4*>(bhv + vBase + 64 + vg * 4);
    const float bvA[4] = {bv0.x, bv0.y, bv0.z, bv0.w};
    const float bvB[4] = {bv1.x, bv1.y, bv1.z, bv1.w};
#pragma unroll
    for (int bi = 0; bi < 4; bi++) {
        const int b = bg * 4 + bi;
        const float* ub = u_t + (size_t)b * V_ + vBase;
        float4 u0 = *reinterpret_cast<const float4*>(ub + vg * 4);
        float4 u1 = *reinterpret_cast<const float4*>(ub + 64 + vg * 4);
        const float uA[4] = {u0.x, u0.y, u0.z, u0.w};
        const float uB[4] = {u1.x, u1.y, u1.z, u1.w};
        float best = -3.402823466e38f;
        int bestV = 0;
#pragma unroll
        for (int e = 0; e < 4; e++) {
            float gn = -logf(-logf(uA[e] + 1e-10f) + 1e-10f);
            float s = acc[e][bi] + bvA[e] + gn;
            int v = vBase + vg * 4 + e;
            if (s > best) { best = s; bestV = v; }
        }
#pragma unroll
        for (int e = 0; e < 4; e++) {
            float gn = -logf(-logf(uB[e] + 1e-10f) + 1e-10f);
            float s = acc[4 + e][bi] + bvB[e] + gn;
            int v = vBase + 64 + vg * 4 + e;
            if (s > best) { best = s; bestV = v; }
        }
        redS[b * 16 + vg] = best;
        redI[b * 16 + vg] = bestV;
    }
    __syncthreads();
    if (tid < 32) {
        float bb = redS[tid * 16];
        int   bi = redI[tid * 16];
#pragma unroll
        for (int j = 1; j < 16; j++) {
            float s = redS[tid * 16 + j];
            int   v = redI[tid * 16 + j];
            if (s > bb || (s == bb && v < bi)) { bb = s; bi = v; }
        }
        g_pScore[blockIdx.x * B_ + tid] = bb;
        g_pIdx[blockIdx.x * B_ + tid]   = bi;
    }
}

// ================= LSTM step v2 =================
// Block covers m-range [blk*8, +8) x 4 gates = 32 rows x 32 b.
// Thread tile 4 rows x 2 b. K = 512 (emb gather) + 1024 (h).
__global__ __launch_bounds__(128) void lstm_kernel(
        int cur,
        const float* __restrict__ emb,
        const float* __restrict__ Wih,
        const float* __restrict__ Whh,
        const float* __restrict__ bih,
        const float* __restrict__ bhh,
        int useArgmax, int tstep) {
    __shared__ float sWt[2][KC * 32];   // [k][tile row]
    __shared__ float sXh[2][KC * 32];   // [k][b]
    __shared__ float gateS[32 * 32];    // [tile row][b]
    __shared__ int   labelS[B_];
    __shared__ float rs[4 * 32];
    __shared__ int   ri[4 * 32];

    const int tid = threadIdx.x;
    const int jg = tid & 7;             // 8 row-groups of 4
    const int bg = tid >> 3;            // 16 b-groups of 2
    const int m0 = blockIdx.x * 8;

    // ---- prologue: deterministic final argmax over 250 partials (redundant per block) ----
    if (useArgmax) {
        int r = tid & 3, b = tid >> 2;
        float bb = -3.402823466e38f;
        int   bi = 0x7fffffff;
        for (int j = r; j < NBLK_V; j += 4) {
            float s = g_pScore[j * B_ + b];
            int   v = g_pIdx[j * B_ + b];
            if (s > bb || (s == bb && v < bi)) { bb = s; bi = v; }
        }
        rs[r * 32 + b] = bb; ri[r * 32 + b] = bi;
        __syncthreads();
        if (tid < 32) {
            float m = rs[tid]; int mi = ri[tid];
#pragma unroll
            for (int r2 = 1; r2 < 4; r2++) {
                float s = rs[r2 * 32 + tid];
                int   v = ri[r2 * 32 + tid];
                if (s > m || (s == m && v < mi)) { m = s; mi = v; }
            }
            labelS[tid] = mi;
            if (blockIdx.x == 0) g_labels[tstep * B_ + tid] = mi;
        }
    } else {
        if (tid < 32) labelS[tid] = BOS_;
    }
    __syncthreads();

    const float* __restrict__ hin = g_h[cur];
    float* __restrict__ hout = g_h[cur ^ 1];

    // staging roles: W -> (tile row r = tid&31, quarter q = tid>>5)
    //                xh -> (b = tid>>2, quarter xq = tid&3)
    const int r  = tid & 31, q = tid >> 5;
    const int gR = r >> 3, mm = r & 7;
    const float* __restrict__ rowIh = Wih + (size_t)(gR * H_ + m0 + mm) * E_;
    const float* __restrict__ rowHh = Whh + (size_t)(gR * H_ + m0 + mm) * H_;
    const int xb = tid >> 2, xq = tid & 3;
    const float* __restrict__ embRow = emb + (size_t)labelS[xb] * E_;

    float acc[4][2];
#pragma unroll
    for (int i = 0; i < 4; i++) { acc[i][0] = 0.f; acc[i][1] = 0.f; }

    float4 wrg, xrg;
    // preload chunk 0 (k in [0,16): emb region)
    wrg = *reinterpret_cast<const float4*>(rowIh + q * 4);
    xrg = *reinterpret_cast<const float4*>(embRow + xq * 4);
    {
        float* dW = &sWt[0][0];
        dW[(q * 4 + 0) * 32 + r] = wrg.x; dW[(q * 4 + 1) * 32 + r] = wrg.y;
        dW[(q * 4 + 2) * 32 + r] = wrg.z; dW[(q * 4 + 3) * 32 + r] = wrg.w;
        float* dX = &sXh[0][0];
        dX[(xq * 4 + 0) * 32 + xb] = xrg.x; dX[(xq * 4 + 1) * 32 + xb] = xrg.y;
        dX[(xq * 4 + 2) * 32 + xb] = xrg.z; dX[(xq * 4 + 3) * 32 + xb] = xrg.w;
    }
    __syncthreads();

    const int NT = (E_ + H_) / KC;   // 96 ; chunks 0..31 = emb, 32..95 = h
    for (int c = 0; c < NT; c++) {
        const int cb = c & 1, nb = (c + 1) & 1;
        if (c + 1 < NT) {
            const int cn = c + 1;
            const float* wsrc = (cn < 32) ? rowIh + cn * KC + q * 4
                                          : rowHh + (cn - 32) * KC + q * 4;
            const float* xsrc = (cn < 32) ? embRow + cn * KC + xq * 4
                                          : hin + (size_t)xb * H_ + (cn - 32) * KC + xq * 4;
            wrg = *reinterpret_cast<const float4*>(wsrc);
            xrg = *reinterpret_cast<const float4*>(xsrc);
        }
        const float* cW = &sWt[cb][0];
        const float* cX = &sXh[cb][0];
#pragma unroll
        for (int k = 0; k < KC; k++) {
            float4 w4 = *reinterpret_cast<const float4*>(cW + k * 32 + jg * 4);
            float2 h2 = *reinterpret_cast<const float2*>(cX + k * 32 + bg * 2);
            acc[0][0] = fmaf(w4.x, h2.x, acc[0][0]); acc[0][1] = fmaf(w4.x, h2.y, acc[0][1]);
            acc[1][0] = fmaf(w4.y, h2.x, acc[1][0]); acc[1][1] = fmaf(w4.y, h2.y, acc[1][1]);
            acc[2][0] = fmaf(w4.z, h2.x, acc[2][0]); acc[2][1] = fmaf(w4.z, h2.y, acc[2][1]);
            acc[3][0] = fmaf(w4.w, h2.x, acc[3][0]); acc[3][1] = fmaf(w4.w, h2.y, acc[3][1]);
        }
        if (c + 1 < NT) {
            float* dW = &sWt[nb][0];
            dW[(q * 4 + 0) * 32 + r] = wrg.x; dW[(q * 4 + 1) * 32 + r] = wrg.y;
            dW[(q * 4 + 2) * 32 + r] = wrg.z; dW[(q * 4 + 3) * 32 + r] = wrg.w;
            float* dX = &sXh[nb][0];
            dX[(xq * 4 + 0) * 32 + xb] = xrg.x; dX[(xq * 4 + 1) * 32 + xb] = xrg.y;
            dX[(xq * 4 + 2) * 32 + xb] = xrg.z; dX[(xq * 4 + 3) * 32 + xb] = xrg.w;
        }
        __syncthreads();
    }

    // ---- gather gates through smem, fused activation ----
#pragma unroll
    for (int vi = 0; vi < 4; vi++) {
#pragma unroll
        for (int bi = 0; bi < 2; bi++)
            gateS[(jg * 4 + vi) * 32 + bg * 2 + bi] = acc[vi][bi];
    }
    __syncthreads();
#pragma unroll
    for (int it = 0; it < 2; it++) {
        int p = it * 128 + tid;
        int m = p >> 5, b = p & 31;
        int mg = m0 + m;
        float gi = gateS[(m) * 32 + b]      + bih[mg]           + bhh[mg];
        float gf = gateS[(8 + m) * 32 + b]  + bih[H_ + mg]      + bhh[H_ + mg];
        float gg = gateS[(16 + m) * 32 + b] + bih[2 * H_ + mg]  + bhh[2 * H_ + mg];
        float go = gateS[(24 + m) * 32 + b] + bih[3 * H_ + mg]  + bhh[3 * H_ + mg];
        float co = g_c[b * H_ + mg];
        float cn = sigm_(gf) * co + sigm_(gi) * tanhf(gg);
        float hn = sigm_(go) * tanhf(cn);
        g_c[b * H_ + mg] = cn;
        hout[b * H_ + mg] = hn;
    }
}

// ---------------- h0 = image_hidden @ W_proj^T + b_proj ; c = 0 (runs once) ----------------
__global__ __launch_bounds__(128) void inith_kernel(
        const float* __restrict__ img,
        const float* __restrict__ Wproj,
        const float* __restrict__ bproj) {
    __shared__ float sT[128 * 33];
    const int tid = threadIdx.x, lane = tid & 31, w = tid >> 5;
    const int m0 = blockIdx.x * 8 + w * 2;
    float a0 = 0.f, a1 = 0.f;
    for (int dc = 0; dc < 1024; dc += 128) {
        for (int idx = tid; idx < B_ * 128; idx += 128) {
            int b = idx >> 7, k = idx & 127;
            sT[k * 33 + b] = img[b * 1024 + dc + k];
        }
        __syncthreads();
#pragma unroll 2
        for (int k4 = 0; k4 < 32; k4++) {
            float x0 = sT[(k4 * 4 + 0) * 33 + lane];
            float x1 = sT[(k4 * 4 + 1) * 33 + lane];
            float x2 = sT[(k4 * 4 + 2) * 33 + lane];
            float x3 = sT[(k4 * 4 + 3) * 33 + lane];
            float4 w0 = *reinterpret_cast<const float4*>(
                Wproj + (size_t)m0 * 1024 + dc + k4 * 4);
            float4 w1 = *reinterpret_cast<const float4*>(
                Wproj + (size_t)(m0 + 1) * 1024 + dc + k4 * 4);
            a0 = fmaf(w0.x, x0, fmaf(w0.y, x1, fmaf(w0.z, x2, fmaf(w0.w, x3, a0))));
            a1 = fmaf(w1.x, x0, fmaf(w1.y, x1, fmaf(w1.z, x2, fmaf(w1.w, x3, a1))));
        }
        __syncthreads();
    }
    g_h[0][lane * H_ + m0]     = a0 + bproj[m0];
    g_h[0][lane * H_ + m0 + 1] = a1 + bproj[m0 + 1];
    g_c[lane * H_ + m0]     = 0.f;
    g_c[lane * H_ + m0 + 1] = 0.f;
}

// ---------------- zero-fill the logits region ----------------
__global__ void zero_kernel(float4* __restrict__ p, long long n4) {
    long long i = (long long)blockIdx.x * blockDim.x + threadIdx.x;
    long long stride = (long long)gridDim.x * blockDim.x;
    float4 z = make_float4(0.f, 0.f, 0.f, 0.f);
    for (; i < n4; i += stride) p[i] = z;
}

// ---------------- assemble outputs ----------------
__global__ __launch_bounds__(256) void final_kernel(float* __restrict__ out) {
    __shared__ int fe[B_];
    const int tid = threadIdx.x;
    if (tid < B_) {
        int f = T_ - 1;
        for (int t = 0; t < T_ - 1; t++) {
            if (g_labels[t * B_ + tid] == EOS_) { f = t; break; }
        }
        fe[tid] = f;
        out[(long long)B_ * T_ + (long long)B_ * T_ * V_ + tid] = (float)(f + 1);
    }
    __syncthreads();
    for (int idx = tid; idx < B_ * T_; idx += 256) {
        int b = idx >> 6, t = idx & 63;
        int lab = (t == T_ - 1) ? EOS_ : g_labels[t * B_ + b];
        int f = fe[b];
        out[b * T_ + t] = (t < f) ? (float)lab : 0.f;
        int col = (t < f) ? lab : 0;
        out[(long long)B_ * T_ + (long long)(b * T_ + t) * V_ + col] = 1.0f;
    }
}

// ---------------- host launcher ----------------
extern "C" void kernel_launch(void* const* d_in, const int* in_sizes, int n_in,
                              void* d_out, int out_size) {
    const float* img   = (const float*)d_in[0];
    const float* gum   = (const float*)d_in[1];
    const float* Wproj = (const float*)d_in[2];
    const float* bproj = (const float*)d_in[3];
    const float* emb   = (const float*)d_in[4];
    const float* Wih   = (const float*)d_in[5];
    const float* Whh   = (const float*)d_in[6];
    const float* bih   = (const float*)d_in[7];
    const float* bhh   = (const float*)d_in[8];
    const float* Whv   = (const float*)d_in[9];
    const float* bhv   = (const float*)d_in[10];
    float* out = (float*)d_out;

    zero_kernel<<<4096, 256>>>(reinterpret_cast<float4*>(out + B_ * T_),
                               (long long)B_ * T_ * V_ / 4);

    inith_kernel<<<128, 128>>>(img, Wproj, bproj);
    lstm_kernel<<<128, 128>>>(0, emb, Wih, Whh, bih, bhh, /*useArgmax=*/0, 0);

    int cur = 1;
    for (int t = 0; t < T_ - 1; t++) {
        score_kernel<<<NBLK_V, 128>>>(cur, Whv, bhv, gum + (size_t)t * B_ * V_);
        lstm_kernel<<<128, 128>>>(cur, emb, Wih, Whh, bih, bhh, /*useArgmax=*/1, t);
        cur ^= 1;
    }

    final_kernel<<<1, 256>>>(out);
}